// round 1
// baseline (speedup 1.0000x reference)
#include <cuda_runtime.h>
#include <cstdint>

#define BB    16
#define NPP   4096
#define CIN   64
#define MM    1024
#define KK    64
#define HIDN  64
#define OUTC  128
#define NCENT (BB*MM)     // 16384
#define NPTS  (BB*NPP)    // 65536
#define R2F   0.04f
#define CAP   512

// scratch (no allocations allowed)
__device__ __align__(256) float g_pf[(size_t)NPTS*HIDN];   // feat @ W1[:64] + b1, per point
__device__ int   g_nbr[NCENT*KK];
__device__ int   g_cnt[NCENT];

// ---------------------------------------------------------------------------
// Kernel 1: farthest point sampling, one block per cloud.
// Points + running min-distance live in registers; pos also mirrored in smem
// only so the reduction winner's coords can be fetched by one lane.
// ---------------------------------------------------------------------------
__global__ void __launch_bounds__(1024,1)
fps_kernel(const float* __restrict__ point, float* __restrict__ ocent,
           float* __restrict__ obatch)
{
    extern __shared__ float sm[];
    float* px = sm;
    float* py = sm + NPP;
    float* pz = sm + 2*NPP;
    __shared__ unsigned long long s_wb[32];
    __shared__ float s_cx, s_cy, s_cz;

    const int b = blockIdx.x;
    const int t = threadIdx.x;
    const float* pp = point + (size_t)b*NPP*3;

    float lx[4], ly[4], lz[4], ld[4];
    #pragma unroll
    for (int q=0;q<4;q++){
        int i = t + q*1024;
        float x = pp[3*i], y = pp[3*i+1], z = pp[3*i+2];
        px[i]=x; py[i]=y; pz[i]=z;
        lx[q]=x; ly[q]=y; lz[q]=z; ld[q]=3.402823466e38f;
    }
    if (t==0){
        float x=pp[0], y=pp[1], z=pp[2];
        s_cx=x; s_cy=y; s_cz=z;
        size_t o = (size_t)(b*MM)*3;
        ocent[o]=x; ocent[o+1]=y; ocent[o+2]=z;
        obatch[b*MM]=(float)b;
    }
    __syncthreads();
    float cx=s_cx, cy=s_cy, cz=s_cz;
    const int lane = t & 31, warp = t >> 5;

    for (int m=1;m<MM;m++){
        unsigned bestv = 0u; int besti = 0x7fffffff;
        #pragma unroll
        for (int q=0;q<4;q++){
            int i = t + q*1024;
            // no-FMA arithmetic: match "square then sum" elementwise reference
            float dx = __fadd_rn(lx[q], -cx);
            float dy = __fadd_rn(ly[q], -cy);
            float dz = __fadd_rn(lz[q], -cz);
            float d2 = __fadd_rn(__fadd_rn(__fmul_rn(dx,dx), __fmul_rn(dy,dy)),
                                 __fmul_rn(dz,dz));
            float dn = fminf(ld[q], d2);
            ld[q] = dn;
            unsigned vb = __float_as_uint(dn);       // dn >= 0 -> monotonic bits
            if (vb > bestv || (vb == bestv && i < besti)) { bestv = vb; besti = i; }
        }
        // warp argmax (first-index tie-break like jnp.argmax)
        unsigned wmax = __reduce_max_sync(0xffffffffu, bestv);
        unsigned cand = (bestv==wmax) ? (unsigned)besti : 0xffffffffu;
        unsigned widx = __reduce_min_sync(0xffffffffu, cand);
        if (lane==0) s_wb[warp] = ((unsigned long long)wmax<<32) | widx;
        __syncthreads();
        if (warp==0){
            unsigned long long k = s_wb[lane];
            unsigned v  = (unsigned)(k>>32);
            unsigned id = (unsigned)k;
            unsigned vm = __reduce_max_sync(0xffffffffu, v);
            unsigned im = __reduce_min_sync(0xffffffffu, (v==vm)? id : 0xffffffffu);
            if (lane==0){
                int w = (int)im;
                float x=px[w], y=py[w], z=pz[w];
                s_cx=x; s_cy=y; s_cz=z;
                size_t o = (size_t)(b*MM+m)*3;
                ocent[o]=x; ocent[o+1]=y; ocent[o+2]=z;
                obatch[b*MM+m]=(float)b;
            }
        }
        __syncthreads();
        cx=s_cx; cy=s_cy; cz=s_cz;
    }
}

// ---------------------------------------------------------------------------
// Kernel 2: pf[n] = feat[n] @ W1[:64,:] + b1   (center-independent layer-1 part)
// ---------------------------------------------------------------------------
__global__ void __launch_bounds__(256)
pf_kernel(const float* __restrict__ feat, const float* __restrict__ W1,
          const float* __restrict__ b1)
{
    __shared__ float fs[64][65];
    __shared__ float ws[64][64];
    const int t = threadIdx.x;
    const int r0 = blockIdx.x*64;
    for (int i=t;i<64*64;i+=256){
        int r=i>>6, c=i&63;
        fs[r][c] = feat[(size_t)(r0+r)*64 + c];
        ws[r][c] = W1[i];
    }
    __syncthreads();
    const int r  = t>>2;
    const int cb = (t&3)*16;
    float acc[16];
    #pragma unroll
    for (int i=0;i<16;i++) acc[i] = b1[cb+i];
    #pragma unroll 8
    for (int k=0;k<64;k++){
        float f = fs[r][k];
        #pragma unroll
        for (int i=0;i<16;i++) acc[i] = fmaf(f, ws[k][cb+i], acc[i]);
    }
    float* o = g_pf + (size_t)(r0+r)*64 + cb;
    #pragma unroll
    for (int i=0;i<16;i++) o[i] = acc[i];
}

// ---------------------------------------------------------------------------
// Kernel 3: radius search + K-nearest selection by rank-counting.
// 8 centers per block, cloud cached in smem. key = d2bits<<32 | idx gives the
// same ordering/tie-break as top_k(-where(valid,d2,inf)).
// ---------------------------------------------------------------------------
__global__ void __launch_bounds__(256,1)
nbr_kernel(const float* __restrict__ point, const float* __restrict__ cent)
{
    extern __shared__ float sm[];
    float* px = sm;
    float* py = sm + NPP;
    float* pz = sm + 2*NPP;
    unsigned long long* keys = (unsigned long long*)(sm + 3*NPP);
    __shared__ int s_cnt;

    const int t  = threadIdx.x;
    const int c0 = blockIdx.x*8;
    const int b  = c0 / MM;
    const float* pp = point + (size_t)b*NPP*3;
    for (int i=t;i<NPP;i+=256){ px[i]=pp[3*i]; py[i]=pp[3*i+1]; pz[i]=pp[3*i+2]; }
    __syncthreads();

    for (int cc=0; cc<8; cc++){
        const int c = c0+cc;
        const float cx = cent[(size_t)c*3+0];
        const float cy = cent[(size_t)c*3+1];
        const float cz = cent[(size_t)c*3+2];
        if (t==0) s_cnt=0;
        __syncthreads();
        for (int i=t;i<NPP;i+=256){
            float dx = __fadd_rn(cx, -px[i]);
            float dy = __fadd_rn(cy, -py[i]);
            float dz = __fadd_rn(cz, -pz[i]);
            float d2 = __fadd_rn(__fadd_rn(__fmul_rn(dx,dx), __fmul_rn(dy,dy)),
                                 __fmul_rn(dz,dz));
            if (d2 < R2F){
                int p = atomicAdd(&s_cnt, 1);
                if (p < CAP)
                    keys[p] = ((unsigned long long)__float_as_uint(d2)<<32) | (unsigned)i;
            }
        }
        __syncthreads();
        int nc = min(s_cnt, CAP);
        for (int ci=t; ci<nc; ci+=256){
            unsigned long long k = keys[ci];
            int rank = 0;
            for (int m2=0; m2<nc; m2++) rank += (keys[m2] < k) ? 1 : 0;
            if (rank < KK)
                g_nbr[(size_t)c*KK + rank] = b*NPP + (int)(unsigned)(k & 0xffffffffu);
        }
        if (t==0) g_cnt[c] = min(nc, KK);
        __syncthreads();
    }
}

// ---------------------------------------------------------------------------
// Kernel 4: MLP + max aggregation. 4 centers per block, 256 threads.
// Phase A: thread = (center, neighbor): h1 = relu(pf[j] + (p-c)@W1[64:67]);
//          h2 = relu(h1 @ W2 + b2) -> smem.
// Phase B: thread = output column (W3 column in regs), max over neighbors.
// ---------------------------------------------------------------------------
__global__ void __launch_bounds__(256,2)
mlp_kernel(const float* __restrict__ point, const float* __restrict__ cent,
           const float* __restrict__ W1,   const float* __restrict__ b2,
           const float* __restrict__ W3,   const float* __restrict__ b3,
           const float* __restrict__ W2,   float* __restrict__ out)
{
    extern __shared__ float sm[];
    float* W2s = sm;             // 4096 floats
    float* h2s = sm + 4096;      // 4*64*64 floats
    float* w1p = sm + 20480;     // 3*64
    float* b2s = sm + 20672;     // 64
    __shared__ float s_cx[4], s_cy[4], s_cz[4];
    __shared__ int   s_n[4];

    const int t  = threadIdx.x;
    const int c0 = blockIdx.x*4;

    for (int i=t;i<4096;i+=256) W2s[i]=W2[i];
    for (int i=t;i<192;i+=256)  w1p[i]=W1[64*64 + i];
    if (t<64) b2s[t]=b2[t];
    if (t<4){
        int c=c0+t;
        s_n[t]=g_cnt[c];
        s_cx[t]=cent[(size_t)c*3+0];
        s_cy[t]=cent[(size_t)c*3+1];
        s_cz[t]=cent[(size_t)c*3+2];
    }
    __syncthreads();

    { // ---- Phase A ----
        const int ci = t>>6, j = t&63;
        const int c  = c0+ci;
        if (j < s_n[ci]){
            float h1[64];
            const int n = g_nbr[(size_t)c*KK + j];
            const float4* pf4 = reinterpret_cast<const float4*>(g_pf + (size_t)n*HIDN);
            #pragma unroll
            for (int q=0;q<16;q++){
                float4 v = pf4[q];
                h1[4*q+0]=v.x; h1[4*q+1]=v.y; h1[4*q+2]=v.z; h1[4*q+3]=v.w;
            }
            const float dx = point[3*(size_t)n+0] - s_cx[ci];
            const float dy = point[3*(size_t)n+1] - s_cy[ci];
            const float dz = point[3*(size_t)n+2] - s_cz[ci];
            #pragma unroll
            for (int q=0;q<16;q++){
                float4 wx = *(const float4*)(w1p +       4*q);
                float4 wy = *(const float4*)(w1p +  64 + 4*q);
                float4 wz = *(const float4*)(w1p + 128 + 4*q);
                h1[4*q+0] = fmaf(dx,wx.x, fmaf(dy,wy.x, fmaf(dz,wz.x, h1[4*q+0])));
                h1[4*q+1] = fmaf(dx,wx.y, fmaf(dy,wy.y, fmaf(dz,wz.y, h1[4*q+1])));
                h1[4*q+2] = fmaf(dx,wx.z, fmaf(dy,wy.z, fmaf(dz,wz.z, h1[4*q+2])));
                h1[4*q+3] = fmaf(dx,wx.w, fmaf(dy,wy.w, fmaf(dz,wz.w, h1[4*q+3])));
            }
            #pragma unroll
            for (int k=0;k<64;k++) h1[k] = fmaxf(h1[k], 0.0f);

            float* hrow = h2s + ((size_t)ci*64 + j)*64;
            #pragma unroll 1
            for (int c4=0;c4<16;c4++){
                float4 acc = *(const float4*)(b2s + 4*c4);
                #pragma unroll
                for (int k=0;k<64;k++){
                    float4 w = *(const float4*)(W2s + k*64 + 4*c4);
                    acc.x = fmaf(h1[k], w.x, acc.x);
                    acc.y = fmaf(h1[k], w.y, acc.y);
                    acc.z = fmaf(h1[k], w.z, acc.z);
                    acc.w = fmaf(h1[k], w.w, acc.w);
                }
                acc.x=fmaxf(acc.x,0.f); acc.y=fmaxf(acc.y,0.f);
                acc.z=fmaxf(acc.z,0.f); acc.w=fmaxf(acc.w,0.f);
                *(float4*)(hrow + 4*c4) = acc;
            }
        }
    }
    __syncthreads();

    { // ---- Phase B ----
        const int c = t & 127;
        const int g = t >> 7;
        float w3r[64];
        #pragma unroll
        for (int k=0;k<64;k++) w3r[k] = W3[k*OUTC + c];
        const float b3c = b3[c];
        for (int cc=g; cc<4; cc+=2){
            const int cnt = s_n[cc];
            const float* hb = h2s + (size_t)cc*64*64;
            float mx = __int_as_float(0xff800000);   // -inf (cnt>=1 always)
            for (int j=0;j<cnt;j++){
                const float4* hr = (const float4*)(hb + (size_t)j*64);
                float a0=b3c, a1=0.f, a2=0.f, a3=0.f;
                #pragma unroll
                for (int k4=0;k4<16;k4++){
                    float4 h = hr[k4];
                    a0 = fmaf(h.x, w3r[4*k4+0], a0);
                    a1 = fmaf(h.y, w3r[4*k4+1], a1);
                    a2 = fmaf(h.z, w3r[4*k4+2], a2);
                    a3 = fmaf(h.w, w3r[4*k4+3], a3);
                }
                float v = fmaxf((a0+a1)+(a2+a3), 0.0f);
                mx = fmaxf(mx, v);
            }
            out[(size_t)(c0+cc)*OUTC + c] = mx;
        }
    }
}

// ---------------------------------------------------------------------------
extern "C" void kernel_launch(void* const* d_in, const int* in_sizes, int n_in,
                              void* d_out, int out_size)
{
    const float *xyz=0, *point=0, *W1=0, *b1=0, *W2=0, *b2=0, *W3=0, *b3=0;
    int seen64 = 0;
    for (int i=0;i<n_in;i++){
        switch (in_sizes[i]){
            case NPTS*CIN:        xyz   = (const float*)d_in[i]; break;  // 4194304
            case NPTS*3:          point = (const float*)d_in[i]; break;  // 196608
            case (CIN+3)*HIDN:    W1    = (const float*)d_in[i]; break;  // 4288
            case HIDN*HIDN:       W2    = (const float*)d_in[i]; break;  // 4096
            case HIDN*OUTC:       W3    = (const float*)d_in[i]; break;  // 8192
            case HIDN:            if (seen64++==0) b1=(const float*)d_in[i];
                                  else             b2=(const float*)d_in[i]; break;
            case OUTC:            b3    = (const float*)d_in[i]; break;  // 128
            default: break;  // batch (65536), num_samples (1) unused
        }
    }
    (void)out_size;
    float* out    = (float*)d_out;
    float* ocent  = out   + (size_t)NCENT*OUTC;   // centers after features
    float* obatch = ocent + (size_t)NCENT*3;      // batch ids last

    cudaFuncSetAttribute(fps_kernel, cudaFuncAttributeMaxDynamicSharedMemorySize, 3*NPP*4);
    cudaFuncSetAttribute(nbr_kernel, cudaFuncAttributeMaxDynamicSharedMemorySize, 3*NPP*4 + CAP*8);
    cudaFuncSetAttribute(mlp_kernel, cudaFuncAttributeMaxDynamicSharedMemorySize, 20736*4);

    fps_kernel<<<BB, 1024, 3*NPP*4>>>(point, ocent, obatch);
    pf_kernel <<<NPTS/64, 256>>>(xyz, W1, b1);
    nbr_kernel<<<NCENT/8, 256, 3*NPP*4 + CAP*8>>>(point, ocent);
    mlp_kernel<<<NCENT/4, 256, 20736*4>>>(point, ocent, W1, b2, W3, b3, W2, out);
}

// round 8
// speedup vs baseline: 1.8538x; 1.8538x over previous
#include <cuda_runtime.h>
#include <cuda_fp16.h>
#include <cstdint>

#define BB    16
#define NPP   4096
#define CIN   64
#define MM    1024
#define KK    64
#define HIDN  64
#define OUTC  128
#define NCENT (BB*MM)     // 16384
#define NPTS  (BB*NPP)    // 65536
#define R2F   0.04f
#define CAP   512

// scratch (no allocations allowed)
__device__ __align__(256) float g_pf[(size_t)NPTS*HIDN];   // feat @ W1[:64] + b1
__device__ int   g_nbr[NCENT*KK];
__device__ int   g_cnt[NCENT];
#define AST 72                                              // padded row stride (halves)
__device__ __align__(16) __half g_w2h[64*AST];              // W2^T fp16 [n][k] pad-72
__device__ __align__(16) __half g_w3h[128*AST];             // W3^T fp16 [n][k] pad-72

// ---------------- helpers ----------------
__device__ __forceinline__ uint32_t smem_u32(const void* p){
    uint32_t a;
    asm("{ .reg .u64 t; cvta.to.shared.u64 t, %1; cvt.u32.u64 %0, t; }" : "=r"(a) : "l"(p));
    return a;
}
__device__ __forceinline__ void ldsm_x4(uint32_t* r, uint32_t a){
    asm volatile("ldmatrix.sync.aligned.m8n8.x4.shared.b16 {%0,%1,%2,%3}, [%4];"
        : "=r"(r[0]),"=r"(r[1]),"=r"(r[2]),"=r"(r[3]) : "r"(a));
}
// weights are [n][k] with k contiguous -> B fragment is the NON-trans x2 load
__device__ __forceinline__ void ldsm_x2(uint32_t& b0, uint32_t& b1, uint32_t a){
    asm volatile("ldmatrix.sync.aligned.m8n8.x2.shared.b16 {%0,%1}, [%2];"
        : "=r"(b0),"=r"(b1) : "r"(a));
}
__device__ __forceinline__ void mma16816(float* d, const uint32_t* a, uint32_t b0, uint32_t b1){
    asm volatile("mma.sync.aligned.m16n8k16.row.col.f32.f16.f16.f32 "
        "{%0,%1,%2,%3}, {%4,%5,%6,%7}, {%8,%9}, {%0,%1,%2,%3};"
        : "+f"(d[0]),"+f"(d[1]),"+f"(d[2]),"+f"(d[3])
        : "r"(a[0]),"r"(a[1]),"r"(a[2]),"r"(a[3]), "r"(b0),"r"(b1));
}
static __device__ __forceinline__ uint32_t f2h2(float a, float b){
    __half2 h = __floats2half2_rn(a, b);
    return *reinterpret_cast<uint32_t*>(&h);
}

// ---------------------------------------------------------------------------
// Kernel 1: farthest point sampling, one block per cloud (unchanged, passing)
// ---------------------------------------------------------------------------
__global__ void __launch_bounds__(1024,1)
fps_kernel(const float* __restrict__ point, float* __restrict__ ocent,
           float* __restrict__ obatch)
{
    extern __shared__ float sm[];
    float* px = sm;
    float* py = sm + NPP;
    float* pz = sm + 2*NPP;
    __shared__ unsigned long long s_wb[32];
    __shared__ float s_cx, s_cy, s_cz;

    const int b = blockIdx.x;
    const int t = threadIdx.x;
    const float* pp = point + (size_t)b*NPP*3;

    float lx[4], ly[4], lz[4], ld[4];
    #pragma unroll
    for (int q=0;q<4;q++){
        int i = t + q*1024;
        float x = pp[3*i], y = pp[3*i+1], z = pp[3*i+2];
        px[i]=x; py[i]=y; pz[i]=z;
        lx[q]=x; ly[q]=y; lz[q]=z; ld[q]=3.402823466e38f;
    }
    if (t==0){
        float x=pp[0], y=pp[1], z=pp[2];
        s_cx=x; s_cy=y; s_cz=z;
        size_t o = (size_t)(b*MM)*3;
        ocent[o]=x; ocent[o+1]=y; ocent[o+2]=z;
        obatch[b*MM]=(float)b;
    }
    __syncthreads();
    float cx=s_cx, cy=s_cy, cz=s_cz;
    const int lane = t & 31, warp = t >> 5;

    for (int m=1;m<MM;m++){
        unsigned bestv = 0u; int besti = 0x7fffffff;
        #pragma unroll
        for (int q=0;q<4;q++){
            int i = t + q*1024;
            float dx = __fadd_rn(lx[q], -cx);
            float dy = __fadd_rn(ly[q], -cy);
            float dz = __fadd_rn(lz[q], -cz);
            float d2 = __fadd_rn(__fadd_rn(__fmul_rn(dx,dx), __fmul_rn(dy,dy)),
                                 __fmul_rn(dz,dz));
            float dn = fminf(ld[q], d2);
            ld[q] = dn;
            unsigned vb = __float_as_uint(dn);
            if (vb > bestv || (vb == bestv && i < besti)) { bestv = vb; besti = i; }
        }
        unsigned wmax = __reduce_max_sync(0xffffffffu, bestv);
        unsigned cand = (bestv==wmax) ? (unsigned)besti : 0xffffffffu;
        unsigned widx = __reduce_min_sync(0xffffffffu, cand);
        if (lane==0) s_wb[warp] = ((unsigned long long)wmax<<32) | widx;
        __syncthreads();
        if (warp==0){
            unsigned long long k = s_wb[lane];
            unsigned v  = (unsigned)(k>>32);
            unsigned id = (unsigned)k;
            unsigned vm = __reduce_max_sync(0xffffffffu, v);
            unsigned im = __reduce_min_sync(0xffffffffu, (v==vm)? id : 0xffffffffu);
            if (lane==0){
                int w = (int)im;
                float x=px[w], y=py[w], z=pz[w];
                s_cx=x; s_cy=y; s_cz=z;
                size_t o = (size_t)(b*MM+m)*3;
                ocent[o]=x; ocent[o+1]=y; ocent[o+2]=z;
                obatch[b*MM+m]=(float)b;
            }
        }
        __syncthreads();
        cx=s_cx; cy=s_cy; cz=s_cz;
    }
}

// ---------------------------------------------------------------------------
// Kernel 2: pf[n] = feat[n] @ W1[:64,:] + b1  (unchanged)
// ---------------------------------------------------------------------------
__global__ void __launch_bounds__(256)
pf_kernel(const float* __restrict__ feat, const float* __restrict__ W1,
          const float* __restrict__ b1)
{
    __shared__ float fs[64][65];
    __shared__ float ws[64][64];
    const int t = threadIdx.x;
    const int r0 = blockIdx.x*64;
    for (int i=t;i<64*64;i+=256){
        int r=i>>6, c=i&63;
        fs[r][c] = feat[(size_t)(r0+r)*64 + c];
        ws[r][c] = W1[i];
    }
    __syncthreads();
    const int r  = t>>2;
    const int cb = (t&3)*16;
    float acc[16];
    #pragma unroll
    for (int i=0;i<16;i++) acc[i] = b1[cb+i];
    #pragma unroll 8
    for (int k=0;k<64;k++){
        float f = fs[r][k];
        #pragma unroll
        for (int i=0;i<16;i++) acc[i] = fmaf(f, ws[k][cb+i], acc[i]);
    }
    float* o = g_pf + (size_t)(r0+r)*64 + cb;
    #pragma unroll
    for (int i=0;i<16;i++) o[i] = acc[i];
}

// ---------------------------------------------------------------------------
// Kernel 3: radius search + K-nearest by rank-counting (unchanged)
// ---------------------------------------------------------------------------
__global__ void __launch_bounds__(256,1)
nbr_kernel(const float* __restrict__ point, const float* __restrict__ cent)
{
    extern __shared__ float sm[];
    float* px = sm;
    float* py = sm + NPP;
    float* pz = sm + 2*NPP;
    unsigned long long* keys = (unsigned long long*)(sm + 3*NPP);
    __shared__ int s_cnt;

    const int t  = threadIdx.x;
    const int c0 = blockIdx.x*8;
    const int b  = c0 / MM;
    const float* pp = point + (size_t)b*NPP*3;
    for (int i=t;i<NPP;i+=256){ px[i]=pp[3*i]; py[i]=pp[3*i+1]; pz[i]=pp[3*i+2]; }
    __syncthreads();

    for (int cc=0; cc<8; cc++){
        const int c = c0+cc;
        const float cx = cent[(size_t)c*3+0];
        const float cy = cent[(size_t)c*3+1];
        const float cz = cent[(size_t)c*3+2];
        if (t==0) s_cnt=0;
        __syncthreads();
        for (int i=t;i<NPP;i+=256){
            float dx = __fadd_rn(cx, -px[i]);
            float dy = __fadd_rn(cy, -py[i]);
            float dz = __fadd_rn(cz, -pz[i]);
            float d2 = __fadd_rn(__fadd_rn(__fmul_rn(dx,dx), __fmul_rn(dy,dy)),
                                 __fmul_rn(dz,dz));
            if (d2 < R2F){
                int p = atomicAdd(&s_cnt, 1);
                if (p < CAP)
                    keys[p] = ((unsigned long long)__float_as_uint(d2)<<32) | (unsigned)i;
            }
        }
        __syncthreads();
        int nc = min(s_cnt, CAP);
        for (int ci=t; ci<nc; ci+=256){
            unsigned long long k = keys[ci];
            int rank = 0;
            for (int m2=0; m2<nc; m2++) rank += (keys[m2] < k) ? 1 : 0;
            if (rank < KK)
                g_nbr[(size_t)c*KK + rank] = b*NPP + (int)(unsigned)(k & 0xffffffffu);
        }
        if (t==0) g_cnt[c] = min(nc, KK);
        __syncthreads();
    }
}

// ---------------------------------------------------------------------------
// Kernel 3.5: W2^T / W3^T -> fp16 padded [n][AST] tiles
// ---------------------------------------------------------------------------
__global__ void __launch_bounds__(256)
prep_kernel(const float* __restrict__ W2, const float* __restrict__ W3)
{
    const int t = threadIdx.x;
    for (int idx=t; idx<64*64; idx+=256){
        int k = idx>>6, n = idx&63;
        g_w2h[n*AST + k] = __float2half_rn(W2[idx]);
    }
    for (int idx=t; idx<64*128; idx+=256){
        int k = idx>>7, n = idx&127;
        g_w3h[n*AST + k] = __float2half_rn(W3[idx]);
    }
}

// ---------------------------------------------------------------------------
// Kernel 4: HMMA MLP. 4 centers/block (M=256), 256 threads = 8 warps,
// warp w owns rows [32w,32w+32). center = w>>1.
// ---------------------------------------------------------------------------
#define B2_OFF  0
#define B3_OFF  9216
#define A_OFF   27648
#define PM_OFF  64512
#define B2F_OFF 68608
#define B3F_OFF 68864
#define MLP_SMEM 69376

__global__ void __launch_bounds__(256,2)
mlp_kernel(const float* __restrict__ point, const float* __restrict__ cent,
           const float* __restrict__ W1,   const float* __restrict__ b2,
           const float* __restrict__ b3,   float* __restrict__ out)
{
    extern __shared__ char smc[];
    const uint32_t sb = smem_u32(smc);
    __shared__ float w1p[192];
    __shared__ int   s_n[4];
    __shared__ float s_cx[4], s_cy[4], s_cz[4];

    const int t    = threadIdx.x;
    const int warp = t >> 5, lane = t & 31;
    const int gid  = lane >> 2, qid = lane & 3;
    const int c0   = blockIdx.x*4;

    // stage weights / biases
    {
        const uint4* s2 = (const uint4*)g_w2h; uint4* d2 = (uint4*)(smc + B2_OFF);
        for (int i=t; i<576; i+=256)  d2[i] = s2[i];
        const uint4* s3 = (const uint4*)g_w3h; uint4* d3 = (uint4*)(smc + B3_OFF);
        for (int i=t; i<1152; i+=256) d3[i] = s3[i];
    }
    if (t < 64)  ((float*)(smc + B2F_OFF))[t] = b2[t];
    if (t < 128) ((float*)(smc + B3F_OFF))[t] = b3[t];
    for (int i=t; i<192; i+=256) w1p[i] = W1[4096 + i];
    if (t < 4){
        int c = c0 + t;
        s_n[t]  = g_cnt[c];
        s_cx[t] = cent[(size_t)c*3+0];
        s_cy[t] = cent[(size_t)c*3+1];
        s_cz[t] = cent[(size_t)c*3+2];
    }
    __syncthreads();

    // ---- build h1 row t (fp16 into A tile, pad-72) ----
    {
        const int ci = t >> 6, j = t & 63;
        float h1[64];
        if (j < s_n[ci]){
            const int n = g_nbr[(size_t)(c0+ci)*KK + j];
            const float4* pf4 = (const float4*)(g_pf + (size_t)n*HIDN);
            #pragma unroll
            for (int q=0;q<16;q++){
                float4 v = pf4[q];
                h1[4*q+0]=v.x; h1[4*q+1]=v.y; h1[4*q+2]=v.z; h1[4*q+3]=v.w;
            }
            const float dx = point[3*(size_t)n+0] - s_cx[ci];
            const float dy = point[3*(size_t)n+1] - s_cy[ci];
            const float dz = point[3*(size_t)n+2] - s_cz[ci];
            #pragma unroll
            for (int q=0;q<16;q++){
                float4 wx = *(const float4*)(w1p +       4*q);
                float4 wy = *(const float4*)(w1p +  64 + 4*q);
                float4 wz = *(const float4*)(w1p + 128 + 4*q);
                h1[4*q+0] = fmaf(dx,wx.x, fmaf(dy,wy.x, fmaf(dz,wz.x, h1[4*q+0])));
                h1[4*q+1] = fmaf(dx,wx.y, fmaf(dy,wy.y, fmaf(dz,wz.y, h1[4*q+1])));
                h1[4*q+2] = fmaf(dx,wx.z, fmaf(dy,wy.z, fmaf(dz,wz.z, h1[4*q+2])));
                h1[4*q+3] = fmaf(dx,wx.w, fmaf(dy,wy.w, fmaf(dz,wz.w, h1[4*q+3])));
            }
            #pragma unroll
            for (int k=0;k<64;k++) h1[k] = fmaxf(h1[k], 0.0f);
        } else {
            #pragma unroll
            for (int k=0;k<64;k++) h1[k] = 0.0f;
        }
        char* arow = smc + A_OFF + (size_t)t*(AST*2);
        #pragma unroll
        for (int i=0;i<8;i++){
            uint4 v;
            v.x = f2h2(h1[8*i+0], h1[8*i+1]);
            v.y = f2h2(h1[8*i+2], h1[8*i+3]);
            v.z = f2h2(h1[8*i+4], h1[8*i+5]);
            v.w = f2h2(h1[8*i+6], h1[8*i+7]);
            *(uint4*)(arow + i*16) = v;
        }
    }
    __syncwarp();

    const uint32_t aBase  = sb + A_OFF;
    const uint32_t b2Base = sb + B2_OFF;
    const uint32_t b3Base = sb + B3_OFF;
    const int rA = warp*32 + ((lane>>3)&1)*8 + (lane&7);   // ldmatrix A row (mt adds 16)
    const int kA = (lane>>4)*8;                            // ldmatrix A k-offset (kt adds 16)
    const int nB = (lane&7);                               // ldmatrix B n row (nt*8 + base)
    const int kB = ((lane>>3)&1)*8;                        // ldmatrix B k-offset

    // ---- GEMM1: h2 = relu(h1 @ W2 + b2), written back to A tile ----
    {
        float acc[16][4];
        #pragma unroll
        for (int i=0;i<16;i++){ acc[i][0]=0.f; acc[i][1]=0.f; acc[i][2]=0.f; acc[i][3]=0.f; }
        #pragma unroll
        for (int kt=0; kt<4; kt++){
            uint32_t a0[4], a1[4];
            ldsm_x4(a0, aBase + (uint32_t)((rA     )*AST + kt*16 + kA)*2);
            ldsm_x4(a1, aBase + (uint32_t)((rA + 16)*AST + kt*16 + kA)*2);
            #pragma unroll
            for (int nt=0; nt<8; nt++){
                uint32_t b0, b1;
                ldsm_x2(b0, b1, b2Base + (uint32_t)((nt*8 + nB)*AST + kt*16 + kB)*2);
                mma16816(acc[nt],   a0, b0, b1);
                mma16816(acc[8+nt], a1, b0, b1);
            }
        }
        const float* b2s = (const float*)(smc + B2F_OFF);
        #pragma unroll
        for (int mt=0; mt<2; mt++){
            #pragma unroll
            for (int nt=0; nt<8; nt++){
                const int col = nt*8 + 2*qid;
                const float ba = b2s[col], bb = b2s[col+1];
                float* a4 = acc[mt*8+nt];
                uint32_t p0 = f2h2(fmaxf(a4[0]+ba,0.f), fmaxf(a4[1]+bb,0.f));
                uint32_t p1 = f2h2(fmaxf(a4[2]+ba,0.f), fmaxf(a4[3]+bb,0.f));
                const int r0 = warp*32 + mt*16 + gid;
                *(uint32_t*)(smc + A_OFF + (size_t)(r0     *AST + col)*2) = p0;
                *(uint32_t*)(smc + A_OFF + (size_t)((r0+8) *AST + col)*2) = p1;
            }
        }
    }
    __syncwarp();

    // ---- GEMM2 (N=128, two halves) + masked in-register row max ----
    {
        const int cnt = s_n[warp>>1];
        const int jb  = (warp&1)*32;
        float* pm = (float*)(smc + PM_OFF) + warp*128;
        #pragma unroll
        for (int h=0; h<2; h++){
            float acc[16][4];
            #pragma unroll
            for (int i=0;i<16;i++){ acc[i][0]=0.f; acc[i][1]=0.f; acc[i][2]=0.f; acc[i][3]=0.f; }
            #pragma unroll
            for (int kt=0; kt<4; kt++){
                uint32_t a0[4], a1[4];
                ldsm_x4(a0, aBase + (uint32_t)((rA     )*AST + kt*16 + kA)*2);
                ldsm_x4(a1, aBase + (uint32_t)((rA + 16)*AST + kt*16 + kA)*2);
                #pragma unroll
                for (int nt=0; nt<8; nt++){
                    uint32_t b0, b1;
                    ldsm_x2(b0, b1, b3Base + (uint32_t)((h*64 + nt*8 + nB)*AST + kt*16 + kB)*2);
                    mma16816(acc[nt],   a0, b0, b1);
                    mma16816(acc[8+nt], a1, b0, b1);
                }
            }
            const float NEG = __int_as_float(0xff800000);
            float cm0[8], cm1[8];
            #pragma unroll
            for (int nt=0; nt<8; nt++){
                float m0 = NEG, m1 = NEG;
                #pragma unroll
                for (int mt=0; mt<2; mt++){
                    const int j0 = jb + mt*16 + gid;
                    const float* a4 = acc[mt*8+nt];
                    if (j0     < cnt){ m0 = fmaxf(m0, a4[0]); m1 = fmaxf(m1, a4[1]); }
                    if (j0 + 8 < cnt){ m0 = fmaxf(m0, a4[2]); m1 = fmaxf(m1, a4[3]); }
                }
                cm0[nt]=m0; cm1[nt]=m1;
            }
            #pragma unroll
            for (int off=4; off<32; off<<=1){
                #pragma unroll
                for (int nt=0; nt<8; nt++){
                    cm0[nt] = fmaxf(cm0[nt], __shfl_xor_sync(0xffffffffu, cm0[nt], off));
                    cm1[nt] = fmaxf(cm1[nt], __shfl_xor_sync(0xffffffffu, cm1[nt], off));
                }
            }
            if (gid == 0){
                #pragma unroll
                for (int nt=0; nt<8; nt++){
                    pm[h*64 + nt*8 + 2*qid    ] = cm0[nt];
                    pm[h*64 + nt*8 + 2*qid + 1] = cm1[nt];
                }
            }
        }
    }
    __syncthreads();

    // ---- combine warp-pair maxima, +b3, relu, store ----
    {
        const float* pm  = (const float*)(smc + PM_OFF);
        const float* b3s = (const float*)(smc + B3F_OFF);
        const int col = t & 127;
        const int p   = (t>>7)*2;
        #pragma unroll
        for (int q=0; q<2; q++){
            const int cc = p + q;
            float v = fmaxf(pm[(2*cc)*128 + col], pm[(2*cc+1)*128 + col]);
            out[(size_t)(c0+cc)*OUTC + col] = fmaxf(v + b3s[col], 0.0f);
        }
    }
}

// ---------------------------------------------------------------------------
extern "C" void kernel_launch(void* const* d_in, const int* in_sizes, int n_in,
                              void* d_out, int out_size)
{
    const float *xyz=0, *point=0, *W1=0, *b1=0, *W2=0, *b2=0, *W3=0, *b3=0;
    int seen64 = 0;
    for (int i=0;i<n_in;i++){
        switch (in_sizes[i]){
            case NPTS*CIN:        xyz   = (const float*)d_in[i]; break;
            case NPTS*3:          point = (const float*)d_in[i]; break;
            case (CIN+3)*HIDN:    W1    = (const float*)d_in[i]; break;
            case HIDN*HIDN:       W2    = (const float*)d_in[i]; break;
            case HIDN*OUTC:       W3    = (const float*)d_in[i]; break;
            case HIDN:            if (seen64++==0) b1=(const float*)d_in[i];
                                  else             b2=(const float*)d_in[i]; break;
            case OUTC:            b3    = (const float*)d_in[i]; break;
            default: break;
        }
    }
    (void)out_size;
    float* out    = (float*)d_out;
    float* ocent  = out   + (size_t)NCENT*OUTC;
    float* obatch = ocent + (size_t)NCENT*3;

    cudaFuncSetAttribute(fps_kernel, cudaFuncAttributeMaxDynamicSharedMemorySize, 3*NPP*4);
    cudaFuncSetAttribute(nbr_kernel, cudaFuncAttributeMaxDynamicSharedMemorySize, 3*NPP*4 + CAP*8);
    cudaFuncSetAttribute(mlp_kernel, cudaFuncAttributeMaxDynamicSharedMemorySize, MLP_SMEM);

    fps_kernel<<<BB, 1024, 3*NPP*4>>>(point, ocent, obatch);
    pf_kernel <<<NPTS/64, 256>>>(xyz, W1, b1);
    prep_kernel<<<1, 256>>>(W2, W3);
    nbr_kernel<<<NCENT/8, 256, 3*NPP*4 + CAP*8>>>(point, ocent);
    mlp_kernel<<<NCENT/4, 256, MLP_SMEM>>>(point, ocent, W1, b2, b3, out);
}

// round 14
// speedup vs baseline: 2.1090x; 1.1377x over previous
#include <cuda_runtime.h>
#include <cuda_fp16.h>
#include <cstdint>

#define BB    16
#define NPP   4096
#define CIN   64
#define MM    1024
#define KK    64
#define HIDN  64
#define OUTC  128
#define NCENT (BB*MM)     // 16384
#define NPTS  (BB*NPP)    // 65536
#define R2F   0.04f
#define CAP   512

// scratch (no allocations allowed)
__device__ __align__(256) float g_pf[(size_t)NPTS*HIDN];   // feat @ W1[:64] + b1
__device__ int   g_nbr[NCENT*KK];
__device__ int   g_cnt[NCENT];
#define AST 72                                              // padded row stride (halves)
__device__ __align__(16) __half g_w2h[64*AST];              // W2^T fp16 [n][k] pad-72
__device__ __align__(16) __half g_w3h[128*AST];             // W3^T fp16 [n][k] pad-72

// ---------------- helpers ----------------
__device__ __forceinline__ uint32_t smem_u32(const void* p){
    uint32_t a;
    asm("{ .reg .u64 t; cvta.to.shared.u64 t, %1; cvt.u32.u64 %0, t; }" : "=r"(a) : "l"(p));
    return a;
}
__device__ __forceinline__ void ldsm_x4(uint32_t* r, uint32_t a){
    asm volatile("ldmatrix.sync.aligned.m8n8.x4.shared.b16 {%0,%1,%2,%3}, [%4];"
        : "=r"(r[0]),"=r"(r[1]),"=r"(r[2]),"=r"(r[3]) : "r"(a));
}
__device__ __forceinline__ void ldsm_x2(uint32_t& b0, uint32_t& b1, uint32_t a){
    asm volatile("ldmatrix.sync.aligned.m8n8.x2.shared.b16 {%0,%1}, [%2];"
        : "=r"(b0),"=r"(b1) : "r"(a));
}
__device__ __forceinline__ void mma16816(float* d, const uint32_t* a, uint32_t b0, uint32_t b1){
    asm volatile("mma.sync.aligned.m16n8k16.row.col.f32.f16.f16.f32 "
        "{%0,%1,%2,%3}, {%4,%5,%6,%7}, {%8,%9}, {%0,%1,%2,%3};"
        : "+f"(d[0]),"+f"(d[1]),"+f"(d[2]),"+f"(d[3])
        : "r"(a[0]),"r"(a[1]),"r"(a[2]),"r"(a[3]), "r"(b0),"r"(b1));
}
static __device__ __forceinline__ uint32_t f2h2(float a, float b){
    __half2 h = __floats2half2_rn(a, b);
    return *reinterpret_cast<uint32_t*>(&h);
}
// ---- packed f32x2 (Blackwell FFMA2; exact per-lane rn rounding) ----
__device__ __forceinline__ uint64_t pk2(float lo, float hi){
    uint64_t r; asm("mov.b64 %0, {%1,%2};" : "=l"(r) : "f"(lo), "f"(hi)); return r;
}
__device__ __forceinline__ void upk2(float& lo, float& hi, uint64_t v){
    asm("mov.b64 {%0,%1}, %2;" : "=f"(lo), "=f"(hi) : "l"(v));
}
__device__ __forceinline__ uint64_t ffma2(uint64_t a, uint64_t b, uint64_t c){
    uint64_t r; asm("fma.rn.f32x2 %0, %1, %2, %3;" : "=l"(r) : "l"(a), "l"(b), "l"(c)); return r;
}

// ---------------------------------------------------------------------------
// Kernel 1: FPS, one block/cloud. f32x2 packed distances (exact roundings),
// ONE barrier/iter via double-buffered warp keys + all-warp final reduce.
// ---------------------------------------------------------------------------
__global__ void __launch_bounds__(1024,1)
fps_kernel(const float* __restrict__ point, float* __restrict__ ocent,
           float* __restrict__ obatch)
{
    extern __shared__ float sm[];
    float* px = sm;
    float* py = sm + NPP;
    float* pz = sm + 2*NPP;
    __shared__ unsigned long long s_wb[2][32];

    const int b = blockIdx.x;
    const int t = threadIdx.x;
    const float* pp = point + (size_t)b*NPP*3;

    float lx[4], ly[4], lz[4], ld[4];
    #pragma unroll
    for (int q=0;q<4;q++){
        int i = t + q*1024;
        float x = pp[3*i], y = pp[3*i+1], z = pp[3*i+2];
        px[i]=x; py[i]=y; pz[i]=z;
        lx[q]=x; ly[q]=y; lz[q]=z; ld[q]=3.402823466e38f;
    }
    uint64_t X2[2], Y2[2], Z2[2];
    X2[0]=pk2(lx[0],lx[1]); X2[1]=pk2(lx[2],lx[3]);
    Y2[0]=pk2(ly[0],ly[1]); Y2[1]=pk2(ly[2],ly[3]);
    Z2[0]=pk2(lz[0],lz[1]); Z2[1]=pk2(lz[2],lz[3]);

    if (t==0){
        size_t o = (size_t)(b*MM)*3;
        ocent[o]=pp[0]; ocent[o+1]=pp[1]; ocent[o+2]=pp[2];
        obatch[b*MM]=(float)b;
    }
    __syncthreads();
    float cx=px[0], cy=py[0], cz=pz[0];

    const uint64_t NEG1 = pk2(-1.0f,-1.0f);
    const uint64_t ONE2 = pk2( 1.0f, 1.0f);
    const int lane = t & 31;
    const int warp = t >> 5;
    int par = 0;

    for (int m=1;m<MM;m++){
        const uint64_t cX=pk2(cx,cx), cY=pk2(cy,cy), cZ=pk2(cz,cz);
        #pragma unroll
        for (int p=0;p<2;p++){
            // per-lane: rn(x-c), rn(d*d), rn(sx+sy), rn(s+sz) — matches reference
            uint64_t dx = ffma2(cX, NEG1, X2[p]);
            uint64_t dy = ffma2(cY, NEG1, Y2[p]);
            uint64_t dz = ffma2(cZ, NEG1, Z2[p]);
            uint64_t sx = ffma2(dx, dx, 0ull);
            uint64_t sy = ffma2(dy, dy, 0ull);
            uint64_t sz = ffma2(dz, dz, 0ull);
            uint64_t s  = ffma2(sy, ONE2, sx);
            uint64_t d2 = ffma2(sz, ONE2, s);
            float a, b2; upk2(a, b2, d2);
            ld[2*p]   = fminf(ld[2*p],   a);
            ld[2*p+1] = fminf(ld[2*p+1], b2);
        }
        // thread-local argmax, ascending index => first-index tie-break
        float bd = ld[0]; int bi = t;
        if (ld[1] > bd){ bd=ld[1]; bi=t+1024; }
        if (ld[2] > bd){ bd=ld[2]; bi=t+2048; }
        if (ld[3] > bd){ bd=ld[3]; bi=t+3072; }

        unsigned bits = __float_as_uint(bd);          // bd >= 0 -> monotonic
        unsigned wmax = __reduce_max_sync(0xffffffffu, bits);
        unsigned cand = (bits==wmax) ? (unsigned)bi : 0xffffffffu;
        unsigned widx = __reduce_min_sync(0xffffffffu, cand);
        if (lane==0) s_wb[par][warp] = ((unsigned long long)wmax<<32) | widx;
        __syncthreads();
        // every warp reduces the 32 warp keys (no second barrier)
        unsigned long long k = s_wb[par][lane];
        unsigned v  = (unsigned)(k>>32);
        unsigned id = (unsigned)k;
        unsigned vm = __reduce_max_sync(0xffffffffu, v);
        unsigned im = __reduce_min_sync(0xffffffffu, (v==vm)? id : 0xffffffffu);
        int w = (int)im;
        cx = px[w]; cy = py[w]; cz = pz[w];
        if (t==0){
            size_t o = (size_t)(b*MM+m)*3;
            ocent[o]=cx; ocent[o+1]=cy; ocent[o+2]=cz;
            obatch[b*MM+m]=(float)b;
        }
        par ^= 1;
    }
}

// ---------------------------------------------------------------------------
// Kernel 2: pf[n] = feat[n] @ W1[:64,:] + b1  (unchanged)
// ---------------------------------------------------------------------------
__global__ void __launch_bounds__(256)
pf_kernel(const float* __restrict__ feat, const float* __restrict__ W1,
          const float* __restrict__ b1)
{
    __shared__ float fs[64][65];
    __shared__ float ws[64][64];
    const int t = threadIdx.x;
    const int r0 = blockIdx.x*64;
    for (int i=t;i<64*64;i+=256){
        int r=i>>6, c=i&63;
        fs[r][c] = feat[(size_t)(r0+r)*64 + c];
        ws[r][c] = W1[i];
    }
    __syncthreads();
    const int r  = t>>2;
    const int cb = (t&3)*16;
    float acc[16];
    #pragma unroll
    for (int i=0;i<16;i++) acc[i] = b1[cb+i];
    #pragma unroll 8
    for (int k=0;k<64;k++){
        float f = fs[r][k];
        #pragma unroll
        for (int i=0;i<16;i++) acc[i] = fmaf(f, ws[k][cb+i], acc[i]);
    }
    float* o = g_pf + (size_t)(r0+r)*64 + cb;
    #pragma unroll
    for (int i=0;i<16;i++) o[i] = acc[i];
}

// ---------------------------------------------------------------------------
// Kernel 3: radius + K-nearest. Points register-resident across 8 centers,
// keys-only smem (4KB), rank-count unroll x2, direct write when nc<=K
// (set-selection only: max-aggregation is order-invariant).
// ---------------------------------------------------------------------------
__global__ void __launch_bounds__(256,3)
nbr_kernel(const float* __restrict__ point, const float* __restrict__ cent)
{
    __shared__ __align__(16) unsigned long long keys[CAP];
    __shared__ int s_cnt;
    __shared__ float s_c[24];

    const int t  = threadIdx.x;
    const int c0 = blockIdx.x*8;
    const int b  = c0 / MM;
    const float* pp = point + (size_t)b*NPP*3;

    float X[16], Y[16], Z[16];
    #pragma unroll
    for (int k=0;k<16;k++){
        int i = t + k*256;
        X[k]=pp[3*i]; Y[k]=pp[3*i+1]; Z[k]=pp[3*i+2];
    }
    if (t < 24) s_c[t] = cent[(size_t)c0*3 + t];

    for (int cc=0; cc<8; cc++){
        if (t==0) s_cnt = 0;
        __syncthreads();
        const float cx=s_c[cc*3+0], cy=s_c[cc*3+1], cz=s_c[cc*3+2];
        #pragma unroll
        for (int k=0;k<16;k++){
            float dx = __fadd_rn(cx, -X[k]);
            float dy = __fadd_rn(cy, -Y[k]);
            float dz = __fadd_rn(cz, -Z[k]);
            float d2 = __fadd_rn(__fadd_rn(__fmul_rn(dx,dx), __fmul_rn(dy,dy)),
                                 __fmul_rn(dz,dz));
            if (d2 < R2F){
                int p = atomicAdd(&s_cnt, 1);
                if (p < CAP)
                    keys[p] = ((unsigned long long)__float_as_uint(d2)<<32)
                            | (unsigned)(t + k*256);
            }
        }
        __syncthreads();
        int nc = min(s_cnt, CAP);
        if (nc <= KK){
            if (t < nc)
                g_nbr[(size_t)(c0+cc)*KK + t] =
                    b*NPP + (int)(unsigned)(keys[t] & 0xffffffffu);
        } else {
            for (int ci=t; ci<nc; ci+=256){
                unsigned long long kk = keys[ci];
                int rank = 0;
                int m2 = 0;
                for (; m2+1 < nc; m2 += 2){
                    unsigned long long a = keys[m2];
                    unsigned long long e = keys[m2+1];
                    rank += (a < kk) ? 1 : 0;
                    rank += (e < kk) ? 1 : 0;
                }
                if (m2 < nc) rank += (keys[m2] < kk) ? 1 : 0;
                if (rank < KK)
                    g_nbr[(size_t)(c0+cc)*KK + rank] =
                        b*NPP + (int)(unsigned)(kk & 0xffffffffu);
            }
        }
        if (t==0) g_cnt[c0+cc] = min(nc, KK);
        __syncthreads();
    }
}

// ---------------------------------------------------------------------------
// Kernel 3.5: W2^T / W3^T -> fp16 padded [n][AST] tiles (unchanged)
// ---------------------------------------------------------------------------
__global__ void __launch_bounds__(256)
prep_kernel(const float* __restrict__ W2, const float* __restrict__ W3)
{
    const int t = threadIdx.x;
    for (int idx=t; idx<64*64; idx+=256){
        int k = idx>>6, n = idx&63;
        g_w2h[n*AST + k] = __float2half_rn(W2[idx]);
    }
    for (int idx=t; idx<64*128; idx+=256){
        int k = idx>>7, n = idx&127;
        g_w3h[n*AST + k] = __float2half_rn(W3[idx]);
    }
}

// ---------------------------------------------------------------------------
// Kernel 4: HMMA MLP (unchanged from 827us pass)
// ---------------------------------------------------------------------------
#define B2_OFF  0
#define B3_OFF  9216
#define A_OFF   27648
#define PM_OFF  64512
#define B2F_OFF 68608
#define B3F_OFF 68864
#define MLP_SMEM 69376

__global__ void __launch_bounds__(256,2)
mlp_kernel(const float* __restrict__ point, const float* __restrict__ cent,
           const float* __restrict__ W1,   const float* __restrict__ b2,
           const float* __restrict__ b3,   float* __restrict__ out)
{
    extern __shared__ char smc[];
    const uint32_t sb = smem_u32(smc);
    __shared__ float w1p[192];
    __shared__ int   s_n[4];
    __shared__ float s_cx[4], s_cy[4], s_cz[4];

    const int t    = threadIdx.x;
    const int warp = t >> 5, lane = t & 31;
    const int gid  = lane >> 2, qid = lane & 3;
    const int c0   = blockIdx.x*4;

    {
        const uint4* s2 = (const uint4*)g_w2h; uint4* d2 = (uint4*)(smc + B2_OFF);
        for (int i=t; i<576; i+=256)  d2[i] = s2[i];
        const uint4* s3 = (const uint4*)g_w3h; uint4* d3 = (uint4*)(smc + B3_OFF);
        for (int i=t; i<1152; i+=256) d3[i] = s3[i];
    }
    if (t < 64)  ((float*)(smc + B2F_OFF))[t] = b2[t];
    if (t < 128) ((float*)(smc + B3F_OFF))[t] = b3[t];
    for (int i=t; i<192; i+=256) w1p[i] = W1[4096 + i];
    if (t < 4){
        int c = c0 + t;
        s_n[t]  = g_cnt[c];
        s_cx[t] = cent[(size_t)c*3+0];
        s_cy[t] = cent[(size_t)c*3+1];
        s_cz[t] = cent[(size_t)c*3+2];
    }
    __syncthreads();

    // ---- build h1 row t (fp16 into A tile, pad-72) ----
    {
        const int ci = t >> 6, j = t & 63;
        float h1[64];
        if (j < s_n[ci]){
            const int n = g_nbr[(size_t)(c0+ci)*KK + j];
            const float4* pf4 = (const float4*)(g_pf + (size_t)n*HIDN);
            #pragma unroll
            for (int q=0;q<16;q++){
                float4 v = pf4[q];
                h1[4*q+0]=v.x; h1[4*q+1]=v.y; h1[4*q+2]=v.z; h1[4*q+3]=v.w;
            }
            const float dx = point[3*(size_t)n+0] - s_cx[ci];
            const float dy = point[3*(size_t)n+1] - s_cy[ci];
            const float dz = point[3*(size_t)n+2] - s_cz[ci];
            #pragma unroll
            for (int q=0;q<16;q++){
                float4 wx = *(const float4*)(w1p +       4*q);
                float4 wy = *(const float4*)(w1p +  64 + 4*q);
                float4 wz = *(const float4*)(w1p + 128 + 4*q);
                h1[4*q+0] = fmaf(dx,wx.x, fmaf(dy,wy.x, fmaf(dz,wz.x, h1[4*q+0])));
                h1[4*q+1] = fmaf(dx,wx.y, fmaf(dy,wy.y, fmaf(dz,wz.y, h1[4*q+1])));
                h1[4*q+2] = fmaf(dx,wx.z, fmaf(dy,wy.z, fmaf(dz,wz.z, h1[4*q+2])));
                h1[4*q+3] = fmaf(dx,wx.w, fmaf(dy,wy.w, fmaf(dz,wz.w, h1[4*q+3])));
            }
            #pragma unroll
            for (int k=0;k<64;k++) h1[k] = fmaxf(h1[k], 0.0f);
        } else {
            #pragma unroll
            for (int k=0;k<64;k++) h1[k] = 0.0f;
        }
        char* arow = smc + A_OFF + (size_t)t*(AST*2);
        #pragma unroll
        for (int i=0;i<8;i++){
            uint4 v;
            v.x = f2h2(h1[8*i+0], h1[8*i+1]);
            v.y = f2h2(h1[8*i+2], h1[8*i+3]);
            v.z = f2h2(h1[8*i+4], h1[8*i+5]);
            v.w = f2h2(h1[8*i+6], h1[8*i+7]);
            *(uint4*)(arow + i*16) = v;
        }
    }
    __syncwarp();

    const uint32_t aBase  = sb + A_OFF;
    const uint32_t b2Base = sb + B2_OFF;
    const uint32_t b3Base = sb + B3_OFF;
    const int rA = warp*32 + ((lane>>3)&1)*8 + (lane&7);
    const int kA = (lane>>4)*8;
    const int nB = (lane&7);
    const int kB = ((lane>>3)&1)*8;

    // ---- GEMM1: h2 = relu(h1 @ W2 + b2), written back to A tile ----
    {
        float acc[16][4];
        #pragma unroll
        for (int i=0;i<16;i++){ acc[i][0]=0.f; acc[i][1]=0.f; acc[i][2]=0.f; acc[i][3]=0.f; }
        #pragma unroll
        for (int kt=0; kt<4; kt++){
            uint32_t a0[4], a1[4];
            ldsm_x4(a0, aBase + (uint32_t)((rA     )*AST + kt*16 + kA)*2);
            ldsm_x4(a1, aBase + (uint32_t)((rA + 16)*AST + kt*16 + kA)*2);
            #pragma unroll
            for (int nt=0; nt<8; nt++){
                uint32_t b0, b1;
                ldsm_x2(b0, b1, b2Base + (uint32_t)((nt*8 + nB)*AST + kt*16 + kB)*2);
                mma16816(acc[nt],   a0, b0, b1);
                mma16816(acc[8+nt], a1, b0, b1);
            }
        }
        const float* b2s = (const float*)(smc + B2F_OFF);
        #pragma unroll
        for (int mt=0; mt<2; mt++){
            #pragma unroll
            for (int nt=0; nt<8; nt++){
                const int col = nt*8 + 2*qid;
                const float ba = b2s[col], bb = b2s[col+1];
                float* a4 = acc[mt*8+nt];
                uint32_t p0 = f2h2(fmaxf(a4[0]+ba,0.f), fmaxf(a4[1]+bb,0.f));
                uint32_t p1 = f2h2(fmaxf(a4[2]+ba,0.f), fmaxf(a4[3]+bb,0.f));
                const int r0 = warp*32 + mt*16 + gid;
                *(uint32_t*)(smc + A_OFF + (size_t)(r0     *AST + col)*2) = p0;
                *(uint32_t*)(smc + A_OFF + (size_t)((r0+8) *AST + col)*2) = p1;
            }
        }
    }
    __syncwarp();

    // ---- GEMM2 (N=128, two halves) + masked in-register row max ----
    {
        const int cnt = s_n[warp>>1];
        const int jb  = (warp&1)*32;
        float* pm = (float*)(smc + PM_OFF) + warp*128;
        #pragma unroll
        for (int h=0; h<2; h++){
            float acc[16][4];
            #pragma unroll
            for (int i=0;i<16;i++){ acc[i][0]=0.f; acc[i][1]=0.f; acc[i][2]=0.f; acc[i][3]=0.f; }
            #pragma unroll
            for (int kt=0; kt<4; kt++){
                uint32_t a0[4], a1[4];
                ldsm_x4(a0, aBase + (uint32_t)((rA     )*AST + kt*16 + kA)*2);
                ldsm_x4(a1, aBase + (uint32_t)((rA + 16)*AST + kt*16 + kA)*2);
                #pragma unroll
                for (int nt=0; nt<8; nt++){
                    uint32_t b0, b1;
                    ldsm_x2(b0, b1, b3Base + (uint32_t)((h*64 + nt*8 + nB)*AST + kt*16 + kB)*2);
                    mma16816(acc[nt],   a0, b0, b1);
                    mma16816(acc[8+nt], a1, b0, b1);
                }
            }
            const float NEG = __int_as_float(0xff800000);
            float cm0[8], cm1[8];
            #pragma unroll
            for (int nt=0; nt<8; nt++){
                float m0 = NEG, m1 = NEG;
                #pragma unroll
                for (int mt=0; mt<2; mt++){
                    const int j0 = jb + mt*16 + gid;
                    const float* a4 = acc[mt*8+nt];
                    if (j0     < cnt){ m0 = fmaxf(m0, a4[0]); m1 = fmaxf(m1, a4[1]); }
                    if (j0 + 8 < cnt){ m0 = fmaxf(m0, a4[2]); m1 = fmaxf(m1, a4[3]); }
                }
                cm0[nt]=m0; cm1[nt]=m1;
            }
            #pragma unroll
            for (int off=4; off<32; off<<=1){
                #pragma unroll
                for (int nt=0; nt<8; nt++){
                    cm0[nt] = fmaxf(cm0[nt], __shfl_xor_sync(0xffffffffu, cm0[nt], off));
                    cm1[nt] = fmaxf(cm1[nt], __shfl_xor_sync(0xffffffffu, cm1[nt], off));
                }
            }
            if (gid == 0){
                #pragma unroll
                for (int nt=0; nt<8; nt++){
                    pm[h*64 + nt*8 + 2*qid    ] = cm0[nt];
                    pm[h*64 + nt*8 + 2*qid + 1] = cm1[nt];
                }
            }
        }
    }
    __syncthreads();

    // ---- combine warp-pair maxima, +b3, relu, store ----
    {
        const float* pm  = (const float*)(smc + PM_OFF);
        const float* b3s = (const float*)(smc + B3F_OFF);
        const int col = t & 127;
        const int p   = (t>>7)*2;
        #pragma unroll
        for (int q=0; q<2; q++){
            const int cc = p + q;
            float v = fmaxf(pm[(2*cc)*128 + col], pm[(2*cc+1)*128 + col]);
            out[(size_t)(c0+cc)*OUTC + col] = fmaxf(v + b3s[col], 0.0f);
        }
    }
}

// ---------------------------------------------------------------------------
extern "C" void kernel_launch(void* const* d_in, const int* in_sizes, int n_in,
                              void* d_out, int out_size)
{
    const float *xyz=0, *point=0, *W1=0, *b1=0, *W2=0, *b2=0, *W3=0, *b3=0;
    int seen64 = 0;
    for (int i=0;i<n_in;i++){
        switch (in_sizes[i]){
            case NPTS*CIN:        xyz   = (const float*)d_in[i]; break;
            case NPTS*3:          point = (const float*)d_in[i]; break;
            case (CIN+3)*HIDN:    W1    = (const float*)d_in[i]; break;
            case HIDN*HIDN:       W2    = (const float*)d_in[i]; break;
            case HIDN*OUTC:       W3    = (const float*)d_in[i]; break;
            case HIDN:            if (seen64++==0) b1=(const float*)d_in[i];
                                  else             b2=(const float*)d_in[i]; break;
            case OUTC:            b3    = (const float*)d_in[i]; break;
            default: break;
        }
    }
    (void)out_size;
    float* out    = (float*)d_out;
    float* ocent  = out   + (size_t)NCENT*OUTC;
    float* obatch = ocent + (size_t)NCENT*3;

    cudaFuncSetAttribute(fps_kernel, cudaFuncAttributeMaxDynamicSharedMemorySize, 3*NPP*4);
    cudaFuncSetAttribute(mlp_kernel, cudaFuncAttributeMaxDynamicSharedMemorySize, MLP_SMEM);

    fps_kernel<<<BB, 1024, 3*NPP*4>>>(point, ocent, obatch);
    pf_kernel <<<NPTS/64, 256>>>(xyz, W1, b1);
    prep_kernel<<<1, 256>>>(W2, W3);
    nbr_kernel<<<NCENT/8, 256>>>(point, ocent);
    mlp_kernel<<<NCENT/4, 256, MLP_SMEM>>>(point, ocent, W1, b2, b3, out);
}